// round 12
// baseline (speedup 1.0000x reference)
#include <cuda_runtime.h>
#include <math.h>

#define TT   512      // frames per batch
#define NLM  51       // landmarks
#define FST  153      // floats per frame (51*3)
#define FPF  114      // features per frame
#define SP   115      // padded out-stage stride (odd -> conflict-free)
#define NF   64       // frames per block
#define BLK  512      // threads per block (8 threads / frame)
#define NWARP (BLK/32)
#define HROWS 68      // NF + 4 halo rows

__device__ __forceinline__ float fsqrt_a(float x){
    float r; asm("sqrt.approx.f32 %0, %1;" : "=f"(r) : "f"(x)); return r;
}

__device__ __forceinline__ float3 f3sub(float3 a, float3 b){ return make_float3(a.x-b.x, a.y-b.y, a.z-b.z); }
__device__ __forceinline__ float3 f3add(float3 a, float3 b){ return make_float3(a.x+b.x, a.y+b.y, a.z+b.z); }
__device__ __forceinline__ float3 f3scale(float3 a, float s){ return make_float3(a.x*s, a.y*s, a.z*s); }
__device__ __forceinline__ float  f3dot(float3 a, float3 b){ return a.x*b.x + a.y*b.y + a.z*b.z; }
__device__ __forceinline__ float3 f3cross(float3 a, float3 b){
    return make_float3(a.y*b.z - a.z*b.y, a.z*b.x - a.x*b.z, a.x*b.y - a.y*b.x);
}
__device__ __forceinline__ float f3norm(float3 v){ return fsqrt_a(f3dot(v,v)); }
__device__ __forceinline__ float distE(float3 a, float3 b){ float3 d = f3sub(a,b); return fsqrt_a(f3dot(d,d) + 1e-6f); }
__device__ __forceinline__ float fdiv(float a, float b){ return __fdividef(a, b); }

// fast acos: A&S 4.4.45 7-term poly; clip matches reference
__device__ __forceinline__ float acosc(float c){
    c = fminf(fmaxf(c, -1.0f + 1e-6f), 1.0f - 1e-6f);
    float ax = fabsf(c);
    float p = -0.0012624911f;
    p = fmaf(p, ax,  0.0066700901f);
    p = fmaf(p, ax, -0.0170881256f);
    p = fmaf(p, ax,  0.0308918810f);
    p = fmaf(p, ax, -0.0501743046f);
    p = fmaf(p, ax,  0.0889789874f);
    p = fmaf(p, ax, -0.2145988016f);
    p = fmaf(p, ax,  1.5707963050f);
    float r = fsqrt_a(1.0f - ax) * p;
    return (c < 0.0f) ? (3.14159265358979f - r) : r;
}

// constant-lm access: folds to [Rbase + imm]
__device__ __forceinline__ float3 sp(const float* __restrict__ base, int lm){
    return make_float3(base[lm*3], base[lm*3+1], base[lm*3+2]);
}
// halo read: lmsel 0->wrist0, 1->wrist21, 2->nose(42); tau in [0,TT-1]
__device__ __forceinline__ float3 hp(const float* __restrict__ sH, int t0, int tau, int lmsel){
    const float* q = sH + (tau - t0 + 2) * 9 + lmsel * 3;
    return make_float3(q[0], q[1], q[2]);
}
__device__ __forceinline__ float3 velH(const float* __restrict__ sH, int t0, int t, int lmsel){
    int tc = t < 1 ? 1 : (t > TT - 2 ? TT - 2 : t);
    float3 a = hp(sH, t0, tc + 1, lmsel);
    float3 c = hp(sH, t0, tc - 1, lmsel);
    return make_float3(0.5f*(a.x-c.x), 0.5f*(a.y-c.y), 0.5f*(a.z-c.z));
}

extern __shared__ float smem_raw[];

__global__ void __launch_bounds__(BLK, 3)
geo_kernel(const float* __restrict__ xyz,
           const float* __restrict__ fmask,
           const float* __restrict__ bmask,
           float* __restrict__ out,
           int BT)
{
    // local compile-time triplet tables -> fold to immediates under unroll
    constexpr int cP[15] = {0,1,2, 0,5,6, 0,9,10, 0,13,14, 0,17,18};
    constexpr int cJ[15] = {1,2,3, 5,6,7, 9,10,11, 13,14,15, 17,18,19};
    constexpr int cC[15] = {2,3,4, 6,7,8, 10,11,12, 14,15,16, 18,19,20};

    float* sIn   = smem_raw;                 // NF*153
    float* sHalo = sIn + NF * FST;           // 68*9
    float* sOut  = sHalo + HROWS * 9;        // NF*115

    const int tid = threadIdx.x;
    const int f   = tid & (NF - 1);          // frame within block
    const int sub = tid >> 6;                // 0..7, whole warps (NF=64)
    const int f0  = blockIdx.x * NF;
    const int bt  = f0 + f;

    const int bi = f0 / TT;
    const int t0 = f0 - bi * TT;

    // ---- stage input frames (coalesced float4) ----
    {
        const float4* gsrc = (const float4*)(xyz + (size_t)f0 * FST);
        float4* sdst = (float4*)sIn;
        #pragma unroll
        for (int i = tid; i < (NF * FST) / 4; i += BLK) sdst[i] = gsrc[i];
    }
    // ---- stage temporal halo ----
    {
        const float* xb = xyz + (size_t)bi * TT * FST;
        for (int i = tid; i < HROWS * 9; i += BLK) {
            int row = i / 9, c = i - row * 9;
            int lmsel = c / 3;
            int lm = (lmsel == 0) ? 0 : (lmsel == 1 ? 21 : 42);
            int tl = t0 - 2 + row;
            tl = tl < 0 ? 0 : (tl > TT - 1 ? TT - 1 : tl);
            sHalo[i] = __ldg(xb + (size_t)tl * FST + lm * 3 + (c - lmsel * 3));
        }
    }
    __syncthreads();

    if (bt < BT) {
        const float* fr = sIn + f * FST;
        float* o = sOut + f * SP;
        const int t = t0 + f;
        const int h    = sub >> 2;           // hand
        const int part = sub & 3;            // 4-way split within hand

        // hand-relative bases: all landmark/feature accesses fold to [R + imm]
        const float* frh  = fr + h * 63;     // landmark (h*21 + X) -> frh + X
        float* ofo  = o + h * 12;            // tips/curls block
        float* oang = o + 34 + h * 15;       // joint angle block

        const float3 w0 = sp(fr, 0);
        const float3 w1 = sp(fr, 21);
        const float3 wH = sp(frh, 0);

        if (part == 0) {
            // ---- tips + cross ----
            float3 tT = sp(frh, 4),  tI = sp(frh, 8),  tM = sp(frh, 12);
            float3 tR = sp(frh, 16), tP = sp(frh, 20);
            ofo[0] = distE(tT, tI);
            ofo[1] = distE(tI, tM);
            ofo[2] = distE(tM, tR);
            ofo[3] = distE(tR, tP);
            ofo[4] = distE(tT, tP);
            ofo[10] = tI.x - tM.x;

            // ---- joint angles k=0..4 ----
            #pragma unroll
            for (int k = 0; k < 5; ++k) {
                float3 vp = sp(frh, cP[k]);
                float3 vj = sp(frh, cJ[k]);
                float3 vc = sp(frh, cC[k]);
                float3 v1 = f3sub(vp, vj), v2 = f3sub(vc, vj);
                float den = fsqrt_a(f3dot(v1, v1) * f3dot(v2, v2)) + 1e-6f;
                oang[k] = acosc(fdiv(f3dot(v1, v2), den));
            }

            // ---- body block (masked) ----
            const float bg = __ldg(bmask + bt);
            float3 lsh = sp(fr, 45), rsh = sp(fr, 46);
            float shmx = 0.5f * (lsh.x + rsh.x);
            float shmy = 0.5f * (lsh.y + rsh.y);
            float shw  = distE(lsh, rsh);
            float si   = fdiv(1.0f, shw + 1e-6f);
            float3 mo = f3scale(f3add(sp(fr, 49), sp(fr, 50)), 0.5f);
            if (h == 0) {
                float3 lel = sp(fr, 47);
                o[103] = (w0.y - shmy) * si * bg;
                o[104] = (w0.x - shmx) * si * bg;
                o[105] = distE(w0, lsh) * bg;
                o[106] = distE(w0, lel) * bg;
                o[111] = shw * bg;
                o[112] = distE(w0, mo) * bg;
            } else {
                float3 rel = sp(fr, 48);
                o[107] = (w1.y - shmy) * si * bg;
                o[108] = (w1.x - shmx) * si * bg;
                o[109] = distE(w1, rsh) * bg;
                o[110] = distE(w1, rel) * bg;
                o[113] = distE(w1, mo) * bg;
            }
        } else if (part == 1) {
            // ---- joint angles k=5..9 ----
            #pragma unroll
            for (int k = 5; k < 10; ++k) {
                float3 vp = sp(frh, cP[k]);
                float3 vj = sp(frh, cJ[k]);
                float3 vc = sp(frh, cC[k]);
                float3 v1 = f3sub(vp, vj), v2 = f3sub(vc, vj);
                float den = fsqrt_a(f3dot(v1, v1) * f3dot(v2, v2)) + 1e-6f;
                oang[k] = acosc(fdiv(f3dot(v1, v2), den));
            }

            // ---- face half (masked) ----
            {
                const float fg = __ldg(fmask + bt);
                const float3 nose = sp(fr, 42);
                const float3 chin = sp(fr, 43);
                const float3 fh   = sp(fr, 44);
                const float3 tip  = sp(frh, 8);      // 8 or 29 = 21+8
                float* oface = o + 24 + h * 3;
                oface[0] = distE(wH, nose) * fg;
                oface[1] = distE(wH, chin) * fg;
                oface[2] = distE(wH, fh)   * fg;
                float* otip = o + 30 + h * 2;
                otip[0] = distE(tip, nose) * fg;
                otip[1] = distE(tip, fh)   * fg;
            }

            // ---- x diffs ----
            float* oxd = o + 93 + h * 2;
            oxd[0] = frh[24] - frh[36];              // (8)*3, (12)*3
            oxd[1] = frh[36] - frh[48];              // (12)*3, (16)*3

            if (h == 0) {
                // inter-hand + sigmoid
                o[88] = distE(w0, w1);
                float3 rel = f3sub(w1, w0);
                float rnv = f3norm(rel);
                float ri = fdiv(1.0f, rnv + 1e-6f);
                o[89] = rel.x * ri;
                o[90] = rel.y * ri;
                float xs = 0.25f - 5.0f * rnv;
                o[102] = fdiv(1.0f, 1.0f + __expf(-xs));
            } else {
                // ld . rd
                float3 v0 = velH(sHalo, t0, t, 0);
                float3 v1 = velH(sHalo, t0, t, 1);
                float3 a0 = f3scale(v0, fdiv(1.0f, f3norm(v0) + 1e-6f));
                float3 a1 = f3scale(v1, fdiv(1.0f, f3norm(v1) + 1e-6f));
                o[97] = f3dot(a0, a1);
            }
        } else if (part == 2) {
            // ---- curls + d_ti ----
            {
                float3 tT = sp(frh, 4),  tI = sp(frh, 8),  tM = sp(frh, 12);
                float3 tR = sp(frh, 16), tP = sp(frh, 20);
                float3 m2  = sp(frh, 2),  m5  = sp(frh, 5),  m9  = sp(frh, 9);
                float3 m13 = sp(frh, 13), m17 = sp(frh, 17);
                float3 i3  = sp(frh, 3),  i6  = sp(frh, 6),  i10 = sp(frh, 10);
                float3 i14 = sp(frh, 14), i18 = sp(frh, 18);
                ofo[5] = fdiv(distE(m2,  tT), distE(m2,  i3)  + 1e-4f);
                ofo[6] = fdiv(distE(m5,  tI), distE(m5,  i6)  + 1e-4f);
                ofo[7] = fdiv(distE(m9,  tM), distE(m9,  i10) + 1e-4f);
                ofo[8] = fdiv(distE(m13, tR), distE(m13, i14) + 1e-4f);
                ofo[9] = fdiv(distE(m17, tP), distE(m17, i18) + 1e-4f);
                ofo[11] = distE(tT, m5);
            }
            // ---- joint angles k=10..14 ----
            #pragma unroll
            for (int k = 10; k < 15; ++k) {
                float3 vp = sp(frh, cP[k]);
                float3 vj = sp(frh, cJ[k]);
                float3 vc = sp(frh, cC[k]);
                float3 v1 = f3sub(vp, vj), v2 = f3sub(vc, vj);
                float den = fsqrt_a(f3dot(v1, v1) * f3dot(v2, v2)) + 1e-6f;
                oang[k] = acosc(fdiv(f3dot(v1, v2), den));
            }
        } else {
            // ---- spreads 0..2 + palm normal ----
            {
                float3 v5  = f3sub(sp(frh, 5),  wH);
                float3 v9  = f3sub(sp(frh, 9),  wH);
                float3 v13 = f3sub(sp(frh, 13), wH);
                float3 v17 = f3sub(sp(frh, 17), wH);
                float* osp = o + 70 + h * 3;
                osp[0] = acosc(fdiv(f3dot(v5,  v9 ), fsqrt_a(f3dot(v5,  v5 ) * f3dot(v9,  v9 )) + 1e-6f));
                osp[1] = acosc(fdiv(f3dot(v9,  v13), fsqrt_a(f3dot(v9,  v9 ) * f3dot(v13, v13)) + 1e-6f));
                osp[2] = acosc(fdiv(f3dot(v13, v17), fsqrt_a(f3dot(v13, v13) * f3dot(v17, v17)) + 1e-6f));
                float3 n = f3cross(v5, v17);
                float inv = fdiv(1.0f, f3norm(n) + 1e-6f);
                n = f3scale(n, inv);
                float* onr = o + 64 + h * 3;
                onr[0] = n.x; onr[1] = n.y; onr[2] = n.z;
                float* ouf = o + 76 + h * 2;
                ouf[0] = n.y; ouf[1] = n.z;
            }

            // ---- temporal ----
            float3 vh = velH(sHalo, t0, t, h);
            float nh = f3norm(vh);
            {
                float ih = fdiv(1.0f, fmaxf(nh, 1e-6f));
                float* ovd = o + 80 + h * 3;
                ovd[0] = vh.x * ih; ovd[1] = vh.y * ih; ovd[2] = vh.z * ih;
                o[98 + h] = nh;
            }
            {
                float3 vhn = velH(sHalo, t0, t + 1, h);
                float3 a  = f3scale(vh,  fdiv(1.0f, nh + 1e-6f));
                float3 bb = f3scale(vhn, fdiv(1.0f, f3norm(vhn) + 1e-6f));
                o[86 + h] = (t == TT - 1) ? 0.0f : acosc(f3dot(a, bb));
            }
            {
                int td = t < 1 ? 1 : (t > TT - 2 ? TT - 2 : t);
                float dp = f3norm(f3sub(hp(sHalo, t0, td + 1, h), hp(sHalo, t0, td + 1, 2)));
                float dm = f3norm(f3sub(hp(sHalo, t0, td - 1, h), hp(sHalo, t0, td - 1, 2)));
                o[91 + h] = 0.5f * (dp - dm);
            }
            {
                int tc = t < 1 ? 1 : (t > TT - 2 ? TT - 2 : t);
                float3 ap = velH(sHalo, t0, tc + 1, h);
                float3 am = velH(sHalo, t0, tc - 1, h);
                float3 ac = make_float3(0.5f*(ap.x-am.x), 0.5f*(ap.y-am.y), 0.5f*(ap.z-am.z));
                o[100 + h] = f3norm(ac);
            }
        }
    }

    __syncthreads();

    // ---- coalesced writeback: warp-per-frame, division-free ----
    int nvalid = BT - f0;
    if (nvalid > NF) nvalid = NF;
    if (nvalid <= 0) return;
    const int wid  = tid >> 5;
    const int lane = tid & 31;
    for (int r = wid; r < nvalid; r += NWARP) {
        const float* src = sOut + r * SP;
        float* dst = out + (size_t)(f0 + r) * FPF;
        #pragma unroll
        for (int j = lane; j < FPF; j += 32) dst[j] = src[j];
    }
}

extern "C" void kernel_launch(void* const* d_in, const int* in_sizes, int n_in,
                              void* d_out, int out_size)
{
    const float* xyz = (const float*)d_in[0];
    const float* fm  = (const float*)d_in[1];
    const float* bm  = (const float*)d_in[2];
    float* out = (float*)d_out;

    const int BT = in_sizes[1];
    const int blocks = (BT + NF - 1) / NF;

    const int smem_bytes = (NF * FST + HROWS * 9 + NF * SP) * (int)sizeof(float);
    cudaFuncSetAttribute(geo_kernel, cudaFuncAttributeMaxDynamicSharedMemorySize, smem_bytes);

    geo_kernel<<<blocks, BLK, smem_bytes>>>(xyz, fm, bm, out, BT);
}

// round 13
// speedup vs baseline: 1.0925x; 1.0925x over previous
#include <cuda_runtime.h>
#include <math.h>

#define TT   512      // frames per batch
#define NLM  51       // landmarks
#define FST  153      // floats per frame (51*3)
#define FPF  114      // features per frame
#define SP   115      // padded out-stage stride (odd -> conflict-free)
#define NF   32       // frames per block
#define BLK  256      // threads per block (8 threads / frame)
#define NWARP (BLK/32)
#define HROWS 36      // NF + 4 halo rows

__device__ __forceinline__ float fsqrt_a(float x){
    float r; asm("sqrt.approx.f32 %0, %1;" : "=f"(r) : "f"(x)); return r;
}

__device__ __forceinline__ float3 f3sub(float3 a, float3 b){ return make_float3(a.x-b.x, a.y-b.y, a.z-b.z); }
__device__ __forceinline__ float3 f3add(float3 a, float3 b){ return make_float3(a.x+b.x, a.y+b.y, a.z+b.z); }
__device__ __forceinline__ float3 f3scale(float3 a, float s){ return make_float3(a.x*s, a.y*s, a.z*s); }
__device__ __forceinline__ float  f3dot(float3 a, float3 b){ return a.x*b.x + a.y*b.y + a.z*b.z; }
__device__ __forceinline__ float3 f3cross(float3 a, float3 b){
    return make_float3(a.y*b.z - a.z*b.y, a.z*b.x - a.x*b.z, a.x*b.y - a.y*b.x);
}
__device__ __forceinline__ float f3norm(float3 v){ return fsqrt_a(f3dot(v,v)); }
__device__ __forceinline__ float distE(float3 a, float3 b){ float3 d = f3sub(a,b); return fsqrt_a(f3dot(d,d) + 1e-6f); }
__device__ __forceinline__ float fdiv(float a, float b){ return __fdividef(a, b); }

// fast acos: A&S 4.4.45 7-term poly; clip matches reference
__device__ __forceinline__ float acosc(float c){
    c = fminf(fmaxf(c, -1.0f + 1e-6f), 1.0f - 1e-6f);
    float ax = fabsf(c);
    float p = -0.0012624911f;
    p = fmaf(p, ax,  0.0066700901f);
    p = fmaf(p, ax, -0.0170881256f);
    p = fmaf(p, ax,  0.0308918810f);
    p = fmaf(p, ax, -0.0501743046f);
    p = fmaf(p, ax,  0.0889789874f);
    p = fmaf(p, ax, -0.2145988016f);
    p = fmaf(p, ax,  1.5707963050f);
    float r = fsqrt_a(1.0f - ax) * p;
    return (c < 0.0f) ? (3.14159265358979f - r) : r;
}

// constant-lm access: folds to [Rbase + imm]
__device__ __forceinline__ float3 sp(const float* __restrict__ base, int lm){
    return make_float3(base[lm*3], base[lm*3+1], base[lm*3+2]);
}
// halo read: lmsel 0->wrist0, 1->wrist21, 2->nose(42); tau in [0,TT-1]
__device__ __forceinline__ float3 hp(const float* __restrict__ sH, int t0, int tau, int lmsel){
    const float* q = sH + (tau - t0 + 2) * 9 + lmsel * 3;
    return make_float3(q[0], q[1], q[2]);
}
__device__ __forceinline__ float3 velH(const float* __restrict__ sH, int t0, int t, int lmsel){
    int tc = t < 1 ? 1 : (t > TT - 2 ? TT - 2 : t);
    float3 a = hp(sH, t0, tc + 1, lmsel);
    float3 c = hp(sH, t0, tc - 1, lmsel);
    return make_float3(0.5f*(a.x-c.x), 0.5f*(a.y-c.y), 0.5f*(a.z-c.z));
}

extern __shared__ float smem_raw[];

__global__ void __launch_bounds__(BLK, 6)
geo_kernel(const float* __restrict__ xyz,
           const float* __restrict__ fmask,
           const float* __restrict__ bmask,
           float* __restrict__ out,
           int BT)
{
    // local compile-time triplet tables -> fold to immediates under unroll
    constexpr int cP[15] = {0,1,2, 0,5,6, 0,9,10, 0,13,14, 0,17,18};
    constexpr int cJ[15] = {1,2,3, 5,6,7, 9,10,11, 13,14,15, 17,18,19};
    constexpr int cC[15] = {2,3,4, 6,7,8, 10,11,12, 14,15,16, 18,19,20};

    float* sIn   = smem_raw;                 // NF*153
    float* sHalo = sIn + NF * FST;           // 36*9
    float* sOut  = sHalo + HROWS * 9;        // NF*115

    const int tid = threadIdx.x;
    const int f   = tid & (NF - 1);          // frame within block
    const int sub = tid >> 5;                // 0..7, whole warps
    const int f0  = blockIdx.x * NF;
    const int bt  = f0 + f;

    const int bi = f0 / TT;
    const int t0 = f0 - bi * TT;

    // ---- stage input frames (coalesced float4) ----
    {
        const float4* gsrc = (const float4*)(xyz + (size_t)f0 * FST);
        float4* sdst = (float4*)sIn;
        #pragma unroll
        for (int i = tid; i < (NF * FST) / 4; i += BLK) sdst[i] = gsrc[i];
    }
    // ---- stage temporal halo ----
    {
        const float* xb = xyz + (size_t)bi * TT * FST;
        for (int i = tid; i < HROWS * 9; i += BLK) {
            int row = i / 9, c = i - row * 9;
            int lmsel = c / 3;
            int lm = (lmsel == 0) ? 0 : (lmsel == 1 ? 21 : 42);
            int tl = t0 - 2 + row;
            tl = tl < 0 ? 0 : (tl > TT - 1 ? TT - 1 : tl);
            sHalo[i] = __ldg(xb + (size_t)tl * FST + lm * 3 + (c - lmsel * 3));
        }
    }
    __syncthreads();

    if (bt < BT) {
        const float* fr = sIn + f * FST;
        float* o = sOut + f * SP;
        const int t = t0 + f;
        const int h    = sub >> 2;           // hand
        const int part = sub & 3;            // 4-way split within hand

        // hand-relative bases: all landmark/feature accesses fold to [R + imm]
        const float* frh  = fr + h * 63;     // landmark (h*21 + X) -> frh + X
        float* ofo  = o + h * 12;            // tips/curls block
        float* oang = o + 34 + h * 15;       // joint angle block

        const float3 w0 = sp(fr, 0);
        const float3 w1 = sp(fr, 21);
        const float3 wH = sp(frh, 0);

        if (part == 0) {
            // ---- tips + cross ----
            float3 tT = sp(frh, 4),  tI = sp(frh, 8),  tM = sp(frh, 12);
            float3 tR = sp(frh, 16), tP = sp(frh, 20);
            ofo[0] = distE(tT, tI);
            ofo[1] = distE(tI, tM);
            ofo[2] = distE(tM, tR);
            ofo[3] = distE(tR, tP);
            ofo[4] = distE(tT, tP);
            ofo[10] = tI.x - tM.x;

            // ---- joint angles k=0..4 ----
            #pragma unroll
            for (int k = 0; k < 5; ++k) {
                float3 vp = sp(frh, cP[k]);
                float3 vj = sp(frh, cJ[k]);
                float3 vc = sp(frh, cC[k]);
                float3 v1 = f3sub(vp, vj), v2 = f3sub(vc, vj);
                float den = fsqrt_a(f3dot(v1, v1) * f3dot(v2, v2)) + 1e-6f;
                oang[k] = acosc(fdiv(f3dot(v1, v2), den));
            }

            // ---- body block (masked) ----
            const float bg = __ldg(bmask + bt);
            float3 lsh = sp(fr, 45), rsh = sp(fr, 46);
            float shmx = 0.5f * (lsh.x + rsh.x);
            float shmy = 0.5f * (lsh.y + rsh.y);
            float shw  = distE(lsh, rsh);
            float si   = fdiv(1.0f, shw + 1e-6f);
            float3 mo = f3scale(f3add(sp(fr, 49), sp(fr, 50)), 0.5f);
            if (h == 0) {
                float3 lel = sp(fr, 47);
                o[103] = (w0.y - shmy) * si * bg;
                o[104] = (w0.x - shmx) * si * bg;
                o[105] = distE(w0, lsh) * bg;
                o[106] = distE(w0, lel) * bg;
                o[111] = shw * bg;
                o[112] = distE(w0, mo) * bg;
            } else {
                float3 rel = sp(fr, 48);
                o[107] = (w1.y - shmy) * si * bg;
                o[108] = (w1.x - shmx) * si * bg;
                o[109] = distE(w1, rsh) * bg;
                o[110] = distE(w1, rel) * bg;
                o[113] = distE(w1, mo) * bg;
            }
        } else if (part == 1) {
            // ---- joint angles k=5..9 ----
            #pragma unroll
            for (int k = 5; k < 10; ++k) {
                float3 vp = sp(frh, cP[k]);
                float3 vj = sp(frh, cJ[k]);
                float3 vc = sp(frh, cC[k]);
                float3 v1 = f3sub(vp, vj), v2 = f3sub(vc, vj);
                float den = fsqrt_a(f3dot(v1, v1) * f3dot(v2, v2)) + 1e-6f;
                oang[k] = acosc(fdiv(f3dot(v1, v2), den));
            }

            // ---- face half (masked) ----
            {
                const float fg = __ldg(fmask + bt);
                const float3 nose = sp(fr, 42);
                const float3 chin = sp(fr, 43);
                const float3 fh   = sp(fr, 44);
                const float3 tip  = sp(frh, 8);      // 8 or 29 = 21+8
                float* oface = o + 24 + h * 3;
                oface[0] = distE(wH, nose) * fg;
                oface[1] = distE(wH, chin) * fg;
                oface[2] = distE(wH, fh)   * fg;
                float* otip = o + 30 + h * 2;
                otip[0] = distE(tip, nose) * fg;
                otip[1] = distE(tip, fh)   * fg;
            }

            // ---- x diffs ----
            float* oxd = o + 93 + h * 2;
            oxd[0] = frh[24] - frh[36];              // (8)*3, (12)*3
            oxd[1] = frh[36] - frh[48];              // (12)*3, (16)*3

            if (h == 0) {
                // inter-hand + sigmoid
                o[88] = distE(w0, w1);
                float3 rel = f3sub(w1, w0);
                float rnv = f3norm(rel);
                float ri = fdiv(1.0f, rnv + 1e-6f);
                o[89] = rel.x * ri;
                o[90] = rel.y * ri;
                float xs = 0.25f - 5.0f * rnv;
                o[102] = fdiv(1.0f, 1.0f + __expf(-xs));
            } else {
                // ld . rd
                float3 v0 = velH(sHalo, t0, t, 0);
                float3 v1 = velH(sHalo, t0, t, 1);
                float3 a0 = f3scale(v0, fdiv(1.0f, f3norm(v0) + 1e-6f));
                float3 a1 = f3scale(v1, fdiv(1.0f, f3norm(v1) + 1e-6f));
                o[97] = f3dot(a0, a1);
            }
        } else if (part == 2) {
            // ---- curls + d_ti ----
            {
                float3 tT = sp(frh, 4),  tI = sp(frh, 8),  tM = sp(frh, 12);
                float3 tR = sp(frh, 16), tP = sp(frh, 20);
                float3 m2  = sp(frh, 2),  m5  = sp(frh, 5),  m9  = sp(frh, 9);
                float3 m13 = sp(frh, 13), m17 = sp(frh, 17);
                float3 i3  = sp(frh, 3),  i6  = sp(frh, 6),  i10 = sp(frh, 10);
                float3 i14 = sp(frh, 14), i18 = sp(frh, 18);
                ofo[5] = fdiv(distE(m2,  tT), distE(m2,  i3)  + 1e-4f);
                ofo[6] = fdiv(distE(m5,  tI), distE(m5,  i6)  + 1e-4f);
                ofo[7] = fdiv(distE(m9,  tM), distE(m9,  i10) + 1e-4f);
                ofo[8] = fdiv(distE(m13, tR), distE(m13, i14) + 1e-4f);
                ofo[9] = fdiv(distE(m17, tP), distE(m17, i18) + 1e-4f);
                ofo[11] = distE(tT, m5);
            }
            // ---- joint angles k=10..14 ----
            #pragma unroll
            for (int k = 10; k < 15; ++k) {
                float3 vp = sp(frh, cP[k]);
                float3 vj = sp(frh, cJ[k]);
                float3 vc = sp(frh, cC[k]);
                float3 v1 = f3sub(vp, vj), v2 = f3sub(vc, vj);
                float den = fsqrt_a(f3dot(v1, v1) * f3dot(v2, v2)) + 1e-6f;
                oang[k] = acosc(fdiv(f3dot(v1, v2), den));
            }
        } else {
            // ---- spreads 0..2 + palm normal ----
            {
                float3 v5  = f3sub(sp(frh, 5),  wH);
                float3 v9  = f3sub(sp(frh, 9),  wH);
                float3 v13 = f3sub(sp(frh, 13), wH);
                float3 v17 = f3sub(sp(frh, 17), wH);
                float* osp = o + 70 + h * 3;
                osp[0] = acosc(fdiv(f3dot(v5,  v9 ), fsqrt_a(f3dot(v5,  v5 ) * f3dot(v9,  v9 )) + 1e-6f));
                osp[1] = acosc(fdiv(f3dot(v9,  v13), fsqrt_a(f3dot(v9,  v9 ) * f3dot(v13, v13)) + 1e-6f));
                osp[2] = acosc(fdiv(f3dot(v13, v17), fsqrt_a(f3dot(v13, v13) * f3dot(v17, v17)) + 1e-6f));
                float3 n = f3cross(v5, v17);
                float inv = fdiv(1.0f, f3norm(n) + 1e-6f);
                n = f3scale(n, inv);
                float* onr = o + 64 + h * 3;
                onr[0] = n.x; onr[1] = n.y; onr[2] = n.z;
                float* ouf = o + 76 + h * 2;
                ouf[0] = n.y; ouf[1] = n.z;
            }

            // ---- temporal ----
            float3 vh = velH(sHalo, t0, t, h);
            float nh = f3norm(vh);
            {
                float ih = fdiv(1.0f, fmaxf(nh, 1e-6f));
                float* ovd = o + 80 + h * 3;
                ovd[0] = vh.x * ih; ovd[1] = vh.y * ih; ovd[2] = vh.z * ih;
                o[98 + h] = nh;
            }
            {
                float3 vhn = velH(sHalo, t0, t + 1, h);
                float3 a  = f3scale(vh,  fdiv(1.0f, nh + 1e-6f));
                float3 bb = f3scale(vhn, fdiv(1.0f, f3norm(vhn) + 1e-6f));
                o[86 + h] = (t == TT - 1) ? 0.0f : acosc(f3dot(a, bb));
            }
            {
                int td = t < 1 ? 1 : (t > TT - 2 ? TT - 2 : t);
                float dp = f3norm(f3sub(hp(sHalo, t0, td + 1, h), hp(sHalo, t0, td + 1, 2)));
                float dm = f3norm(f3sub(hp(sHalo, t0, td - 1, h), hp(sHalo, t0, td - 1, 2)));
                o[91 + h] = 0.5f * (dp - dm);
            }
            {
                int tc = t < 1 ? 1 : (t > TT - 2 ? TT - 2 : t);
                float3 ap = velH(sHalo, t0, tc + 1, h);
                float3 am = velH(sHalo, t0, tc - 1, h);
                float3 ac = make_float3(0.5f*(ap.x-am.x), 0.5f*(ap.y-am.y), 0.5f*(ap.z-am.z));
                o[100 + h] = f3norm(ac);
            }
        }
    }

    __syncthreads();

    // ---- coalesced writeback: warp-per-frame, division-free ----
    int nvalid = BT - f0;
    if (nvalid > NF) nvalid = NF;
    if (nvalid <= 0) return;
    const int wid  = tid >> 5;
    const int lane = tid & 31;
    for (int r = wid; r < nvalid; r += NWARP) {
        const float* src = sOut + r * SP;
        float* dst = out + (size_t)(f0 + r) * FPF;
        #pragma unroll
        for (int j = lane; j < FPF; j += 32) dst[j] = src[j];
    }
}

extern "C" void kernel_launch(void* const* d_in, const int* in_sizes, int n_in,
                              void* d_out, int out_size)
{
    const float* xyz = (const float*)d_in[0];
    const float* fm  = (const float*)d_in[1];
    const float* bm  = (const float*)d_in[2];
    float* out = (float*)d_out;

    const int BT = in_sizes[1];
    const int blocks = (BT + NF - 1) / NF;

    const int smem_bytes = (NF * FST + HROWS * 9 + NF * SP) * (int)sizeof(float);
    cudaFuncSetAttribute(geo_kernel, cudaFuncAttributeMaxDynamicSharedMemorySize, smem_bytes);

    geo_kernel<<<blocks, BLK, smem_bytes>>>(xyz, fm, bm, out, BT);
}

// round 15
// speedup vs baseline: 1.1078x; 1.0140x over previous
#include <cuda_runtime.h>
#include <math.h>

#define TT   512      // frames per batch
#define NLM  51       // landmarks
#define FST  153      // floats per frame (51*3)
#define FPF  114      // features per frame
#define SP   115      // padded out-stage stride (odd -> conflict-free)
#define NF   32       // frames per block
#define BLK  256      // threads per block (8 threads / frame)
#define NWARP (BLK/32)
#define HROWS 36      // NF + 4 halo rows

__device__ __forceinline__ float fsqrt_a(float x){
    float r; asm("sqrt.approx.f32 %0, %1;" : "=f"(r) : "f"(x)); return r;
}

__device__ __forceinline__ float3 f3sub(float3 a, float3 b){ return make_float3(a.x-b.x, a.y-b.y, a.z-b.z); }
__device__ __forceinline__ float3 f3add(float3 a, float3 b){ return make_float3(a.x+b.x, a.y+b.y, a.z+b.z); }
__device__ __forceinline__ float3 f3scale(float3 a, float s){ return make_float3(a.x*s, a.y*s, a.z*s); }
__device__ __forceinline__ float  f3dot(float3 a, float3 b){ return a.x*b.x + a.y*b.y + a.z*b.z; }
__device__ __forceinline__ float3 f3cross(float3 a, float3 b){
    return make_float3(a.y*b.z - a.z*b.y, a.z*b.x - a.x*b.z, a.x*b.y - a.y*b.x);
}
__device__ __forceinline__ float f3norm(float3 v){ return fsqrt_a(f3dot(v,v)); }
__device__ __forceinline__ float distE(float3 a, float3 b){ float3 d = f3sub(a,b); return fsqrt_a(f3dot(d,d) + 1e-6f); }
__device__ __forceinline__ float fdiv(float a, float b){ return __fdividef(a, b); }

// fast acos: A&S 4.4.45 7-term poly; clip matches reference
__device__ __forceinline__ float acosc(float c){
    c = fminf(fmaxf(c, -1.0f + 1e-6f), 1.0f - 1e-6f);
    float ax = fabsf(c);
    float p = -0.0012624911f;
    p = fmaf(p, ax,  0.0066700901f);
    p = fmaf(p, ax, -0.0170881256f);
    p = fmaf(p, ax,  0.0308918810f);
    p = fmaf(p, ax, -0.0501743046f);
    p = fmaf(p, ax,  0.0889789874f);
    p = fmaf(p, ax, -0.2145988016f);
    p = fmaf(p, ax,  1.5707963050f);
    float r = fsqrt_a(1.0f - ax) * p;
    return (c < 0.0f) ? (3.14159265358979f - r) : r;
}

// constant-lm access: folds to [Rbase + imm]
__device__ __forceinline__ float3 sp(const float* __restrict__ base, int lm){
    return make_float3(base[lm*3], base[lm*3+1], base[lm*3+2]);
}
// halo read: lmsel 0->wrist0, 1->wrist21, 2->nose(42); tau in [0,TT-1]
__device__ __forceinline__ float3 hp(const float* __restrict__ sH, int t0, int tau, int lmsel){
    const float* q = sH + (tau - t0 + 2) * 9 + lmsel * 3;
    return make_float3(q[0], q[1], q[2]);
}
__device__ __forceinline__ float3 velH(const float* __restrict__ sH, int t0, int t, int lmsel){
    int tc = t < 1 ? 1 : (t > TT - 2 ? TT - 2 : t);
    float3 a = hp(sH, t0, tc + 1, lmsel);
    float3 c = hp(sH, t0, tc - 1, lmsel);
    return make_float3(0.5f*(a.x-c.x), 0.5f*(a.y-c.y), 0.5f*(a.z-c.z));
}

// finger chain (0, M, M+1, M+2, M+3): 3 joint angles from 4 edge vectors.
// Exact vs reference: for triplet (P,J,C), v1·v2 = -(e_i·e_{i+1}).
// Returns the fingertip (landmark M+3).
template<int M>
__device__ __forceinline__ float3 finger_chain(const float* __restrict__ frh, float* __restrict__ oa){
    float3 a = sp(frh, 0);
    float3 b = sp(frh, M), c = sp(frh, M+1), d = sp(frh, M+2), e = sp(frh, M+3);
    float3 e0 = f3sub(b, a), e1 = f3sub(c, b), e2 = f3sub(d, c), e3 = f3sub(e, d);
    float n0 = f3dot(e0, e0), n1 = f3dot(e1, e1), n2 = f3dot(e2, e2), n3 = f3dot(e3, e3);
    oa[0] = acosc(fdiv(-f3dot(e0, e1), fsqrt_a(n0 * n1) + 1e-6f));
    oa[1] = acosc(fdiv(-f3dot(e1, e2), fsqrt_a(n1 * n2) + 1e-6f));
    oa[2] = acosc(fdiv(-f3dot(e2, e3), fsqrt_a(n2 * n3) + 1e-6f));
    return e;
}

extern __shared__ float smem_raw[];

__global__ void __launch_bounds__(BLK, 6)
geo_kernel(const float* __restrict__ xyz,
           const float* __restrict__ fmask,
           const float* __restrict__ bmask,
           float* __restrict__ out,
           int BT)
{
    float* sIn   = smem_raw;                 // NF*153
    float* sHalo = sIn + NF * FST;           // 36*9
    float* sOut  = sHalo + HROWS * 9;        // NF*115

    const int tid = threadIdx.x;
    const int f   = tid & (NF - 1);          // frame within block
    const int sub = tid >> 5;                // 0..7, whole warps
    const int f0  = blockIdx.x * NF;
    const int bt  = f0 + f;

    const int bi = f0 / TT;
    const int t0 = f0 - bi * TT;

    // ---- stage input frames (coalesced float4) ----
    {
        const float4* gsrc = (const float4*)(xyz + (size_t)f0 * FST);
        float4* sdst = (float4*)sIn;
        #pragma unroll
        for (int i = tid; i < (NF * FST) / 4; i += BLK) sdst[i] = gsrc[i];
    }
    // ---- stage temporal halo ----
    {
        const float* xb = xyz + (size_t)bi * TT * FST;
        for (int i = tid; i < HROWS * 9; i += BLK) {
            int row = i / 9, c = i - row * 9;
            int lmsel = c / 3;
            int lm = (lmsel == 0) ? 0 : (lmsel == 1 ? 21 : 42);
            int tl = t0 - 2 + row;
            tl = tl < 0 ? 0 : (tl > TT - 1 ? TT - 1 : tl);
            sHalo[i] = __ldg(xb + (size_t)tl * FST + lm * 3 + (c - lmsel * 3));
        }
    }
    __syncthreads();

    if (bt < BT) {
        const float* fr = sIn + f * FST;
        float* o = sOut + f * SP;
        const int t = t0 + f;
        const int h    = sub >> 2;           // hand
        const int part = sub & 3;            // 4-way split within hand

        // hand-relative bases: all landmark/feature accesses fold to [R + imm]
        const float* frh  = fr + h * 63;     // landmark (h*21 + X) -> frh + X
        float* ofo  = o + h * 12;            // tips/curls block
        float* oang = o + 34 + h * 15;       // joint angle block

        const float3 w0 = sp(fr, 0);
        const float3 w1 = sp(fr, 21);
        const float3 wH = sp(frh, 0);

        if (part == 0) {
            // ---- thumb + index chains (angles k=0..5), tips reuse chain fingertips ----
            float3 tT = finger_chain<1>(frh, oang + 0);   // thumb tip = lm4
            float3 tI = finger_chain<5>(frh, oang + 3);   // index tip = lm8
            float3 tM = sp(frh, 12), tR = sp(frh, 16), tP = sp(frh, 20);
            ofo[0] = distE(tT, tI);
            ofo[1] = distE(tI, tM);
            ofo[2] = distE(tM, tR);
            ofo[3] = distE(tR, tP);
            ofo[4] = distE(tT, tP);
            ofo[10] = tI.x - tM.x;
        } else if (part == 1) {
            // ---- middle + ring chains (angles k=6..11) ----
            finger_chain<9>(frh, oang + 6);
            finger_chain<13>(frh, oang + 9);

            // ---- face half (masked) ----
            {
                const float fg = __ldg(fmask + bt);
                const float3 nose = sp(fr, 42);
                const float3 chin = sp(fr, 43);
                const float3 fh   = sp(fr, 44);
                const float3 tip  = sp(frh, 8);      // 8 or 29 = 21+8
                float* oface = o + 24 + h * 3;
                oface[0] = distE(wH, nose) * fg;
                oface[1] = distE(wH, chin) * fg;
                oface[2] = distE(wH, fh)   * fg;
                float* otip = o + 30 + h * 2;
                otip[0] = distE(tip, nose) * fg;
                otip[1] = distE(tip, fh)   * fg;
            }

            // ---- x diffs ----
            float* oxd = o + 93 + h * 2;
            oxd[0] = frh[24] - frh[36];              // lm8.x - lm12.x
            oxd[1] = frh[36] - frh[48];              // lm12.x - lm16.x

            if (h == 0) {
                // inter-hand + sigmoid
                o[88] = distE(w0, w1);
                float3 rel = f3sub(w1, w0);
                float rnv = f3norm(rel);
                float ri = fdiv(1.0f, rnv + 1e-6f);
                o[89] = rel.x * ri;
                o[90] = rel.y * ri;
                float xs = 0.25f - 5.0f * rnv;
                o[102] = fdiv(1.0f, 1.0f + __expf(-xs));
            } else {
                // ld . rd
                float3 v0 = velH(sHalo, t0, t, 0);
                float3 v1 = velH(sHalo, t0, t, 1);
                float3 a0 = f3scale(v0, fdiv(1.0f, f3norm(v0) + 1e-6f));
                float3 a1 = f3scale(v1, fdiv(1.0f, f3norm(v1) + 1e-6f));
                o[97] = f3dot(a0, a1);
            }
        } else if (part == 2) {
            // ---- pinky chain (angles k=12..14) ----
            float3 tP = finger_chain<17>(frh, oang + 12); // pinky tip = lm20

            // ---- curls + d_ti ----
            {
                float3 tT = sp(frh, 4),  tI = sp(frh, 8),  tM = sp(frh, 12);
                float3 tR = sp(frh, 16);
                float3 m2  = sp(frh, 2),  m5  = sp(frh, 5),  m9  = sp(frh, 9);
                float3 m13 = sp(frh, 13), m17 = sp(frh, 17);
                float3 i3  = sp(frh, 3),  i6  = sp(frh, 6),  i10 = sp(frh, 10);
                float3 i14 = sp(frh, 14), i18 = sp(frh, 18);
                ofo[5] = fdiv(distE(m2,  tT), distE(m2,  i3)  + 1e-4f);
                ofo[6] = fdiv(distE(m5,  tI), distE(m5,  i6)  + 1e-4f);
                ofo[7] = fdiv(distE(m9,  tM), distE(m9,  i10) + 1e-4f);
                ofo[8] = fdiv(distE(m13, tR), distE(m13, i14) + 1e-4f);
                ofo[9] = fdiv(distE(m17, tP), distE(m17, i18) + 1e-4f);
                ofo[11] = distE(tT, m5);
            }

            // ---- body block (masked) ----
            const float bg = __ldg(bmask + bt);
            float3 lsh = sp(fr, 45), rsh = sp(fr, 46);
            float shmx = 0.5f * (lsh.x + rsh.x);
            float shmy = 0.5f * (lsh.y + rsh.y);
            float shw  = distE(lsh, rsh);
            float si   = fdiv(1.0f, shw + 1e-6f);
            float3 mo = f3scale(f3add(sp(fr, 49), sp(fr, 50)), 0.5f);
            if (h == 0) {
                float3 lel = sp(fr, 47);
                o[103] = (w0.y - shmy) * si * bg;
                o[104] = (w0.x - shmx) * si * bg;
                o[105] = distE(w0, lsh) * bg;
                o[106] = distE(w0, lel) * bg;
                o[111] = shw * bg;
                o[112] = distE(w0, mo) * bg;
            } else {
                float3 rel = sp(fr, 48);
                o[107] = (w1.y - shmy) * si * bg;
                o[108] = (w1.x - shmx) * si * bg;
                o[109] = distE(w1, rsh) * bg;
                o[110] = distE(w1, rel) * bg;
                o[113] = distE(w1, mo) * bg;
            }
        } else {
            // ---- spreads 0..2 + palm normal ----
            {
                float3 v5  = f3sub(sp(frh, 5),  wH);
                float3 v9  = f3sub(sp(frh, 9),  wH);
                float3 v13 = f3sub(sp(frh, 13), wH);
                float3 v17 = f3sub(sp(frh, 17), wH);
                float* osp = o + 70 + h * 3;
                osp[0] = acosc(fdiv(f3dot(v5,  v9 ), fsqrt_a(f3dot(v5,  v5 ) * f3dot(v9,  v9 )) + 1e-6f));
                osp[1] = acosc(fdiv(f3dot(v9,  v13), fsqrt_a(f3dot(v9,  v9 ) * f3dot(v13, v13)) + 1e-6f));
                osp[2] = acosc(fdiv(f3dot(v13, v17), fsqrt_a(f3dot(v13, v13) * f3dot(v17, v17)) + 1e-6f));
                float3 n = f3cross(v5, v17);
                float inv = fdiv(1.0f, f3norm(n) + 1e-6f);
                n = f3scale(n, inv);
                float* onr = o + 64 + h * 3;
                onr[0] = n.x; onr[1] = n.y; onr[2] = n.z;
                float* ouf = o + 76 + h * 2;
                ouf[0] = n.y; ouf[1] = n.z;
            }

            // ---- temporal ----
            float3 vh = velH(sHalo, t0, t, h);
            float nh = f3norm(vh);
            {
                float ih = fdiv(1.0f, fmaxf(nh, 1e-6f));
                float* ovd = o + 80 + h * 3;
                ovd[0] = vh.x * ih; ovd[1] = vh.y * ih; ovd[2] = vh.z * ih;
                o[98 + h] = nh;
            }
            {
                float3 vhn = velH(sHalo, t0, t + 1, h);
                float3 a  = f3scale(vh,  fdiv(1.0f, nh + 1e-6f));
                float3 bb = f3scale(vhn, fdiv(1.0f, f3norm(vhn) + 1e-6f));
                o[86 + h] = (t == TT - 1) ? 0.0f : acosc(f3dot(a, bb));
            }
            {
                int td = t < 1 ? 1 : (t > TT - 2 ? TT - 2 : t);
                float dp = f3norm(f3sub(hp(sHalo, t0, td + 1, h), hp(sHalo, t0, td + 1, 2)));
                float dm = f3norm(f3sub(hp(sHalo, t0, td - 1, h), hp(sHalo, t0, td - 1, 2)));
                o[91 + h] = 0.5f * (dp - dm);
            }
            {
                int tc = t < 1 ? 1 : (t > TT - 2 ? TT - 2 : t);
                float3 ap = velH(sHalo, t0, tc + 1, h);
                float3 am = velH(sHalo, t0, tc - 1, h);
                float3 ac = make_float3(0.5f*(ap.x-am.x), 0.5f*(ap.y-am.y), 0.5f*(ap.z-am.z));
                o[100 + h] = f3norm(ac);
            }
        }
    }

    __syncthreads();

    // ---- coalesced writeback: warp-per-frame, division-free ----
    int nvalid = BT - f0;
    if (nvalid > NF) nvalid = NF;
    if (nvalid <= 0) return;
    const int wid  = tid >> 5;
    const int lane = tid & 31;
    for (int r = wid; r < nvalid; r += NWARP) {
        const float* src = sOut + r * SP;
        float* dst = out + (size_t)(f0 + r) * FPF;
        #pragma unroll
        for (int j = lane; j < FPF; j += 32) dst[j] = src[j];
    }
}

extern "C" void kernel_launch(void* const* d_in, const int* in_sizes, int n_in,
                              void* d_out, int out_size)
{
    const float* xyz = (const float*)d_in[0];
    const float* fm  = (const float*)d_in[1];
    const float* bm  = (const float*)d_in[2];
    float* out = (float*)d_out;

    const int BT = in_sizes[1];
    const int blocks = (BT + NF - 1) / NF;

    const int smem_bytes = (NF * FST + HROWS * 9 + NF * SP) * (int)sizeof(float);
    cudaFuncSetAttribute(geo_kernel, cudaFuncAttributeMaxDynamicSharedMemorySize, smem_bytes);

    geo_kernel<<<blocks, BLK, smem_bytes>>>(xyz, fm, bm, out, BT);
}

// round 16
// speedup vs baseline: 1.1524x; 1.0402x over previous
#include <cuda_runtime.h>
#include <math.h>

#define TT   512      // frames per batch
#define NLM  51       // landmarks
#define FST  153      // floats per frame (51*3)
#define FPF  114      // features per frame
#define SP   116      // padded out-stage stride (29f mod 32 distinct -> conflict-free; 16B-aligned rows)
#define NF   32       // frames per block
#define BLK  256      // threads per block (8 threads / frame)
#define NWARP (BLK/32)
#define HROWS 36      // NF + 4 halo rows
#define HSTR 12       // halo row stride (3 float4 slots)

__device__ __forceinline__ float fsqrt_a(float x){
    float r; asm("sqrt.approx.f32 %0, %1;" : "=f"(r) : "f"(x)); return r;
}

__device__ __forceinline__ float3 f3sub(float3 a, float3 b){ return make_float3(a.x-b.x, a.y-b.y, a.z-b.z); }
__device__ __forceinline__ float3 f3add(float3 a, float3 b){ return make_float3(a.x+b.x, a.y+b.y, a.z+b.z); }
__device__ __forceinline__ float3 f3scale(float3 a, float s){ return make_float3(a.x*s, a.y*s, a.z*s); }
__device__ __forceinline__ float  f3dot(float3 a, float3 b){ return a.x*b.x + a.y*b.y + a.z*b.z; }
__device__ __forceinline__ float3 f3cross(float3 a, float3 b){
    return make_float3(a.y*b.z - a.z*b.y, a.z*b.x - a.x*b.z, a.x*b.y - a.y*b.x);
}
__device__ __forceinline__ float f3norm(float3 v){ return fsqrt_a(f3dot(v,v)); }
__device__ __forceinline__ float distE(float3 a, float3 b){ float3 d = f3sub(a,b); return fsqrt_a(f3dot(d,d) + 1e-6f); }
__device__ __forceinline__ float fdiv(float a, float b){ return __fdividef(a, b); }

// fast acos: A&S 4.4.45 7-term poly; clip matches reference
__device__ __forceinline__ float acosc(float c){
    c = fminf(fmaxf(c, -1.0f + 1e-6f), 1.0f - 1e-6f);
    float ax = fabsf(c);
    float p = -0.0012624911f;
    p = fmaf(p, ax,  0.0066700901f);
    p = fmaf(p, ax, -0.0170881256f);
    p = fmaf(p, ax,  0.0308918810f);
    p = fmaf(p, ax, -0.0501743046f);
    p = fmaf(p, ax,  0.0889789874f);
    p = fmaf(p, ax, -0.2145988016f);
    p = fmaf(p, ax,  1.5707963050f);
    float r = fsqrt_a(1.0f - ax) * p;
    return (c < 0.0f) ? (3.14159265358979f - r) : r;
}

// constant-lm access: folds to [Rbase + imm]
__device__ __forceinline__ float3 sp(const float* __restrict__ base, int lm){
    return make_float3(base[lm*3], base[lm*3+1], base[lm*3+2]);
}
// halo read (one LDS.128): lmsel 0->wrist0, 1->wrist21, 2->nose(42); tau in [0,TT-1]
__device__ __forceinline__ float3 hp(const float* __restrict__ sH, int t0, int tau, int lmsel){
    float4 v = *reinterpret_cast<const float4*>(sH + (tau - t0 + 2) * HSTR + lmsel * 4);
    return make_float3(v.x, v.y, v.z);
}
__device__ __forceinline__ float3 velH(const float* __restrict__ sH, int t0, int t, int lmsel){
    int tc = t < 1 ? 1 : (t > TT - 2 ? TT - 2 : t);
    float3 a = hp(sH, t0, tc + 1, lmsel);
    float3 c = hp(sH, t0, tc - 1, lmsel);
    return make_float3(0.5f*(a.x-c.x), 0.5f*(a.y-c.y), 0.5f*(a.z-c.z));
}

// finger chain (0, M, M+1, M+2, M+3): 3 joint angles from 4 edge vectors.
// Exact vs reference: for triplet (P,J,C), v1·v2 = -(e_i·e_{i+1}).
template<int M>
__device__ __forceinline__ float3 finger_chain(const float* __restrict__ frh, float* __restrict__ oa){
    float3 a = sp(frh, 0);
    float3 b = sp(frh, M), c = sp(frh, M+1), d = sp(frh, M+2), e = sp(frh, M+3);
    float3 e0 = f3sub(b, a), e1 = f3sub(c, b), e2 = f3sub(d, c), e3 = f3sub(e, d);
    float n0 = f3dot(e0, e0), n1 = f3dot(e1, e1), n2 = f3dot(e2, e2), n3 = f3dot(e3, e3);
    oa[0] = acosc(fdiv(-f3dot(e0, e1), fsqrt_a(n0 * n1) + 1e-6f));
    oa[1] = acosc(fdiv(-f3dot(e1, e2), fsqrt_a(n1 * n2) + 1e-6f));
    oa[2] = acosc(fdiv(-f3dot(e2, e3), fsqrt_a(n2 * n3) + 1e-6f));
    return e;
}

extern __shared__ float smem_raw[];

__global__ void __launch_bounds__(BLK, 6)
geo_kernel(const float* __restrict__ xyz,
           const float* __restrict__ fmask,
           const float* __restrict__ bmask,
           float* __restrict__ out,
           int BT)
{
    float* sIn   = smem_raw;                 // NF*153
    float* sHalo = sIn + NF * FST;           // 36*12 (padded float4 slots)
    float* sOut  = sHalo + HROWS * HSTR;     // NF*116

    const int tid = threadIdx.x;
    const int f   = tid & (NF - 1);          // frame within block
    const int sub = tid >> 5;                // 0..7, whole warps
    const int f0  = blockIdx.x * NF;
    const int bt  = f0 + f;

    const int bi = f0 / TT;
    const int t0 = f0 - bi * TT;

    // ---- stage input frames (coalesced float4) ----
    {
        const float4* gsrc = (const float4*)(xyz + (size_t)f0 * FST);
        float4* sdst = (float4*)sIn;
        #pragma unroll
        for (int i = tid; i < (NF * FST) / 4; i += BLK) sdst[i] = gsrc[i];
    }
    // ---- stage temporal halo (padded slots; .w unused) ----
    {
        const float* xb = xyz + (size_t)bi * TT * FST;
        for (int i = tid; i < HROWS * 9; i += BLK) {
            int row = i / 9, c = i - row * 9;
            int lmsel = c / 3;
            int comp  = c - lmsel * 3;
            int lm = (lmsel == 0) ? 0 : (lmsel == 1 ? 21 : 42);
            int tl = t0 - 2 + row;
            tl = tl < 0 ? 0 : (tl > TT - 1 ? TT - 1 : tl);
            sHalo[row * HSTR + lmsel * 4 + comp] = __ldg(xb + (size_t)tl * FST + lm * 3 + comp);
        }
    }
    __syncthreads();

    if (bt < BT) {
        const float* fr = sIn + f * FST;
        float* o = sOut + f * SP;
        const int t = t0 + f;
        const int h    = sub >> 2;           // hand
        const int part = sub & 3;            // 4-way split within hand

        // hand-relative bases: all landmark/feature accesses fold to [R + imm]
        const float* frh  = fr + h * 63;     // landmark (h*21 + X) -> frh + X
        float* ofo  = o + h * 12;            // tips/curls block
        float* oang = o + 34 + h * 15;       // joint angle block

        if (part == 0) {
            // ---- thumb + index chains (angles k=0..5), tips reuse chain fingertips ----
            float3 tT = finger_chain<1>(frh, oang + 0);   // thumb tip = lm4
            float3 tI = finger_chain<5>(frh, oang + 3);   // index tip = lm8
            float3 tM = sp(frh, 12), tR = sp(frh, 16), tP = sp(frh, 20);
            ofo[0] = distE(tT, tI);
            ofo[1] = distE(tI, tM);
            ofo[2] = distE(tM, tR);
            ofo[3] = distE(tR, tP);
            ofo[4] = distE(tT, tP);
            ofo[10] = tI.x - tM.x;
        } else if (part == 1) {
            // ---- middle + ring chains (angles k=6..11) ----
            finger_chain<9>(frh, oang + 6);
            finger_chain<13>(frh, oang + 9);

            const float3 wH = sp(frh, 0);

            // ---- face half (masked) ----
            {
                const float fg = __ldg(fmask + bt);
                const float3 nose = sp(fr, 42);
                const float3 chin = sp(fr, 43);
                const float3 fh   = sp(fr, 44);
                const float3 tip  = sp(frh, 8);      // 8 or 29 = 21+8
                float* oface = o + 24 + h * 3;
                oface[0] = distE(wH, nose) * fg;
                oface[1] = distE(wH, chin) * fg;
                oface[2] = distE(wH, fh)   * fg;
                float* otip = o + 30 + h * 2;
                otip[0] = distE(tip, nose) * fg;
                otip[1] = distE(tip, fh)   * fg;
            }

            // ---- x diffs ----
            float* oxd = o + 93 + h * 2;
            oxd[0] = frh[24] - frh[36];              // lm8.x - lm12.x
            oxd[1] = frh[36] - frh[48];              // lm12.x - lm16.x

            if (h == 0) {
                // inter-hand + sigmoid (wH == w0 here)
                const float3 w1v = sp(fr, 21);
                o[88] = distE(wH, w1v);
                float3 rel = f3sub(w1v, wH);
                float rnv = f3norm(rel);
                float ri = fdiv(1.0f, rnv + 1e-6f);
                o[89] = rel.x * ri;
                o[90] = rel.y * ri;
                float xs = 0.25f - 5.0f * rnv;
                o[102] = fdiv(1.0f, 1.0f + __expf(-xs));
            } else {
                // ld . rd
                float3 v0 = velH(sHalo, t0, t, 0);
                float3 v1 = velH(sHalo, t0, t, 1);
                float3 a0 = f3scale(v0, fdiv(1.0f, f3norm(v0) + 1e-6f));
                float3 a1 = f3scale(v1, fdiv(1.0f, f3norm(v1) + 1e-6f));
                o[97] = f3dot(a0, a1);
            }
        } else if (part == 2) {
            // ---- pinky chain (angles k=12..14) ----
            float3 tP = finger_chain<17>(frh, oang + 12); // pinky tip = lm20

            // ---- curls + d_ti ----
            {
                float3 tT = sp(frh, 4),  tI = sp(frh, 8),  tM = sp(frh, 12);
                float3 tR = sp(frh, 16);
                float3 m2  = sp(frh, 2),  m5  = sp(frh, 5),  m9  = sp(frh, 9);
                float3 m13 = sp(frh, 13), m17 = sp(frh, 17);
                float3 i3  = sp(frh, 3),  i6  = sp(frh, 6),  i10 = sp(frh, 10);
                float3 i14 = sp(frh, 14), i18 = sp(frh, 18);
                ofo[5] = fdiv(distE(m2,  tT), distE(m2,  i3)  + 1e-4f);
                ofo[6] = fdiv(distE(m5,  tI), distE(m5,  i6)  + 1e-4f);
                ofo[7] = fdiv(distE(m9,  tM), distE(m9,  i10) + 1e-4f);
                ofo[8] = fdiv(distE(m13, tR), distE(m13, i14) + 1e-4f);
                ofo[9] = fdiv(distE(m17, tP), distE(m17, i18) + 1e-4f);
                ofo[11] = distE(tT, m5);
            }

            // ---- body block (masked); body wrist == this hand's wrist ----
            const float bg = __ldg(bmask + bt);
            const float3 wH = sp(frh, 0);
            float3 lsh = sp(fr, 45), rsh = sp(fr, 46);
            float shmx = 0.5f * (lsh.x + rsh.x);
            float shmy = 0.5f * (lsh.y + rsh.y);
            float shw  = distE(lsh, rsh);
            float si   = fdiv(1.0f, shw + 1e-6f);
            float3 mo = f3scale(f3add(sp(fr, 49), sp(fr, 50)), 0.5f);
            if (h == 0) {
                float3 lel = sp(fr, 47);
                o[103] = (wH.y - shmy) * si * bg;
                o[104] = (wH.x - shmx) * si * bg;
                o[105] = distE(wH, lsh) * bg;
                o[106] = distE(wH, lel) * bg;
                o[111] = shw * bg;
                o[112] = distE(wH, mo) * bg;
            } else {
                float3 rel = sp(fr, 48);
                o[107] = (wH.y - shmy) * si * bg;
                o[108] = (wH.x - shmx) * si * bg;
                o[109] = distE(wH, rsh) * bg;
                o[110] = distE(wH, rel) * bg;
                o[113] = distE(wH, mo) * bg;
            }
        } else {
            const float3 wH = sp(frh, 0);
            // ---- spreads 0..2 + palm normal ----
            {
                float3 v5  = f3sub(sp(frh, 5),  wH);
                float3 v9  = f3sub(sp(frh, 9),  wH);
                float3 v13 = f3sub(sp(frh, 13), wH);
                float3 v17 = f3sub(sp(frh, 17), wH);
                float* osp = o + 70 + h * 3;
                osp[0] = acosc(fdiv(f3dot(v5,  v9 ), fsqrt_a(f3dot(v5,  v5 ) * f3dot(v9,  v9 )) + 1e-6f));
                osp[1] = acosc(fdiv(f3dot(v9,  v13), fsqrt_a(f3dot(v9,  v9 ) * f3dot(v13, v13)) + 1e-6f));
                osp[2] = acosc(fdiv(f3dot(v13, v17), fsqrt_a(f3dot(v13, v13) * f3dot(v17, v17)) + 1e-6f));
                float3 n = f3cross(v5, v17);
                float inv = fdiv(1.0f, f3norm(n) + 1e-6f);
                n = f3scale(n, inv);
                float* onr = o + 64 + h * 3;
                onr[0] = n.x; onr[1] = n.y; onr[2] = n.z;
                float* ouf = o + 76 + h * 2;
                ouf[0] = n.y; ouf[1] = n.z;
            }

            // ---- temporal ----
            float3 vh = velH(sHalo, t0, t, h);
            float nh = f3norm(vh);
            {
                float ih = fdiv(1.0f, fmaxf(nh, 1e-6f));
                float* ovd = o + 80 + h * 3;
                ovd[0] = vh.x * ih; ovd[1] = vh.y * ih; ovd[2] = vh.z * ih;
                o[98 + h] = nh;
            }
            {
                float3 vhn = velH(sHalo, t0, t + 1, h);
                float3 a  = f3scale(vh,  fdiv(1.0f, nh + 1e-6f));
                float3 bb = f3scale(vhn, fdiv(1.0f, f3norm(vhn) + 1e-6f));
                o[86 + h] = (t == TT - 1) ? 0.0f : acosc(f3dot(a, bb));
            }
            {
                int td = t < 1 ? 1 : (t > TT - 2 ? TT - 2 : t);
                float dp = f3norm(f3sub(hp(sHalo, t0, td + 1, h), hp(sHalo, t0, td + 1, 2)));
                float dm = f3norm(f3sub(hp(sHalo, t0, td - 1, h), hp(sHalo, t0, td - 1, 2)));
                o[91 + h] = 0.5f * (dp - dm);
            }
            {
                int tc = t < 1 ? 1 : (t > TT - 2 ? TT - 2 : t);
                float3 ap = velH(sHalo, t0, tc + 1, h);
                float3 am = velH(sHalo, t0, tc - 1, h);
                float3 ac = make_float3(0.5f*(ap.x-am.x), 0.5f*(ap.y-am.y), 0.5f*(ap.z-am.z));
                o[100 + h] = f3norm(ac);
            }
        }
    }

    __syncthreads();

    // ---- coalesced writeback: warp-per-frame, float2 (rows 8B-aligned both sides) ----
    int nvalid = BT - f0;
    if (nvalid > NF) nvalid = NF;
    if (nvalid <= 0) return;
    const int wid  = tid >> 5;
    const int lane = tid & 31;
    for (int r = wid; r < nvalid; r += NWARP) {
        const float2* src = (const float2*)(sOut + r * SP);
        float2* dst = (float2*)(out + (size_t)(f0 + r) * FPF);
        #pragma unroll
        for (int j = lane; j < FPF / 2; j += 32) dst[j] = src[j];
    }
}

extern "C" void kernel_launch(void* const* d_in, const int* in_sizes, int n_in,
                              void* d_out, int out_size)
{
    const float* xyz = (const float*)d_in[0];
    const float* fm  = (const float*)d_in[1];
    const float* bm  = (const float*)d_in[2];
    float* out = (float*)d_out;

    const int BT = in_sizes[1];
    const int blocks = (BT + NF - 1) / NF;

    const int smem_bytes = (NF * FST + HROWS * HSTR + NF * SP) * (int)sizeof(float);
    cudaFuncSetAttribute(geo_kernel, cudaFuncAttributeMaxDynamicSharedMemorySize, smem_bytes);

    geo_kernel<<<blocks, BLK, smem_bytes>>>(xyz, fm, bm, out, BT);
}